// round 6
// baseline (speedup 1.0000x reference)
#include <cuda_runtime.h>
#include <cuda_bf16.h>
#include <cstdint>

// ---------------------------------------------------------------------------
// Problem constants
// ---------------------------------------------------------------------------
#define NPTS   8192
#define CIN    128
#define DDIM   256
#define KNN    16
#define KSEG   32
#define SEGSZ  (NPTS / KSEG)   // 256

#define NODES_PB 8             // nodes per edge-MMA block (M = 8*16 = 128)
#define EM_THREADS 512         // 16 warps: 4 (m) x 4 (n)

// Scratch (device globals — no allocation allowed)
__device__ float g_AB[NPTS * 512];
__device__ int   g_idx[NPTS * KNN];
__device__ float g_cand_d[NPTS * KSEG * KNN];
__device__ int   g_cand_i[NPTS * KSEG * KNN];
__device__ uint32_t g_W2hi32[32768];        // bf16-hi image, row-major [k][n]
__device__ uint32_t g_W2lo32[32768];        // bf16-lo image

// ---------------------------------------------------------------------------
// PTX helpers
// ---------------------------------------------------------------------------
__device__ __forceinline__ uint32_t smem_u32(const void* p) {
    uint32_t a;
    asm("{ .reg .u64 t; cvta.to.shared.u64 t, %1; cvt.u32.u64 %0, t; }"
        : "=r"(a) : "l"(p));
    return a;
}
__device__ __forceinline__ void ldsm_x4(uint32_t& r0, uint32_t& r1,
                                        uint32_t& r2, uint32_t& r3, uint32_t addr) {
    asm volatile("ldmatrix.sync.aligned.m8n8.x4.shared.b16 {%0,%1,%2,%3}, [%4];"
                 : "=r"(r0), "=r"(r1), "=r"(r2), "=r"(r3) : "r"(addr));
}
__device__ __forceinline__ void ldsm_x4_t(uint32_t& r0, uint32_t& r1,
                                          uint32_t& r2, uint32_t& r3, uint32_t addr) {
    asm volatile("ldmatrix.sync.aligned.m8n8.x4.trans.shared.b16 {%0,%1,%2,%3}, [%4];"
                 : "=r"(r0), "=r"(r1), "=r"(r2), "=r"(r3) : "r"(addr));
}
__device__ __forceinline__ void mma_bf16(float& d0, float& d1, float& d2, float& d3,
                                         uint32_t a0, uint32_t a1, uint32_t a2, uint32_t a3,
                                         uint32_t b0, uint32_t b1) {
    asm volatile("mma.sync.aligned.m16n8k16.row.col.f32.bf16.bf16.f32 "
                 "{%0,%1,%2,%3}, {%4,%5,%6,%7}, {%8,%9}, {%0,%1,%2,%3};"
                 : "+f"(d0), "+f"(d1), "+f"(d2), "+f"(d3)
                 : "r"(a0), "r"(a1), "r"(a2), "r"(a3), "r"(b0), "r"(b1));
}
__device__ __forceinline__ uint32_t pack_hi2(float v0, float v1) {
    return ((uint32_t)__bfloat16_as_ushort(__float2bfloat16_rn(v1)) << 16) |
           (uint32_t)__bfloat16_as_ushort(__float2bfloat16_rn(v0));
}
#define CP_ASYNC16(dst, src) \
    asm volatile("cp.async.cg.shared.global [%0], [%1], 16;" \
                 :: "r"(dst), "l"(src) : "memory")
#define CP_ASYNC_COMMIT() asm volatile("cp.async.commit_group;" ::: "memory")
#define CP_ASYNC_WAIT(n)  asm volatile("cp.async.wait_group %0;" :: "n"(n) : "memory")

// ---------------------------------------------------------------------------
// Kernel 1a: per-segment top-16. 2 queries/thread, FMA distance form.
// grid = (NPTS/512, KSEG), block = 256.
// ---------------------------------------------------------------------------
__global__ void __launch_bounds__(256)
knn_part_kernel(const float* __restrict__ pos,
                float* __restrict__ cand_d, int* __restrict__ cand_i) {
    __shared__ float4 s4[SEGSZ];
    const int t  = threadIdx.x;
    const int i1 = blockIdx.x * 512 + t;
    const int i2 = i1 + 256;
    const int s  = blockIdx.y;
    const int j0 = s * SEGSZ;

    const float x1 = pos[i1 * 3 + 0], y1 = pos[i1 * 3 + 1], z1 = pos[i1 * 3 + 2];
    const float x2 = pos[i2 * 3 + 0], y2 = pos[i2 * 3 + 1], z2 = pos[i2 * 3 + 2];
    const float sq1 = fmaf(z1, z1, fmaf(y1, y1, x1 * x1));
    const float sq2 = fmaf(z2, z2, fmaf(y2, y2, x2 * x2));

    {
        const int jj = t;
        const float x = pos[(j0 + jj) * 3 + 0];
        const float y = pos[(j0 + jj) * 3 + 1];
        const float z = pos[(j0 + jj) * 3 + 2];
        s4[jj] = make_float4(x, y, z, fmaf(z, z, fmaf(y, y, x * x)));
    }
    __syncthreads();

    float bd1[KNN], bd2[KNN];
    int   bi1[KNN], bi2[KNN];
#pragma unroll
    for (int q = 0; q < KNN; q++) {
        bd1[q] = 1e30f; bi1[q] = -1;
        bd2[q] = 1e30f; bi2[q] = -1;
    }

#pragma unroll 4
    for (int jj = 0; jj < SEGSZ; jj++) {
        const float4 p = s4[jj];
        const int j = j0 + jj;

        const float dot1 = fmaf(z1, p.z, fmaf(y1, p.y, x1 * p.x));
        float dist1 = fmaf(-2.0f, dot1, sq1 + p.w);
        dist1 = (j == i1) ? 1e30f : dist1;
        if (dist1 < bd1[KNN - 1]) {
            float d = dist1; int id = j;
#pragma unroll
            for (int q = 0; q < KNN; q++) {
                const bool sw = d < bd1[q];
                const float td = bd1[q]; const int ti = bi1[q];
                bd1[q] = sw ? d : td;   bi1[q] = sw ? id : ti;
                d      = sw ? td : d;   id     = sw ? ti : id;
            }
        }

        const float dot2 = fmaf(z2, p.z, fmaf(y2, p.y, x2 * p.x));
        float dist2 = fmaf(-2.0f, dot2, sq2 + p.w);
        dist2 = (j == i2) ? 1e30f : dist2;
        if (dist2 < bd2[KNN - 1]) {
            float d = dist2; int id = j;
#pragma unroll
            for (int q = 0; q < KNN; q++) {
                const bool sw = d < bd2[q];
                const float td = bd2[q]; const int ti = bi2[q];
                bd2[q] = sw ? d : td;   bi2[q] = sw ? id : ti;
                d      = sw ? td : d;   id     = sw ? ti : id;
            }
        }
    }

    const int base1 = (i1 * KSEG + s) * KNN;
    const int base2 = (i2 * KSEG + s) * KNN;
#pragma unroll
    for (int q = 0; q < KNN; q++) {
        cand_d[base1 + q] = bd1[q];  cand_i[base1 + q] = bi1[q];
        cand_d[base2 + q] = bd2[q];  cand_i[base2 + q] = bi2[q];
    }
}

// ---------------------------------------------------------------------------
// Kernel 1b: merge KSEG sorted candidate lists
// ---------------------------------------------------------------------------
__global__ void __launch_bounds__(256)
knn_merge_kernel(const float* __restrict__ cand_d, const int* __restrict__ cand_i,
                 int* __restrict__ idxout) {
    const int i = blockIdx.x * 256 + threadIdx.x;

    float bd[KNN];
    int   bi[KNN];
#pragma unroll
    for (int q = 0; q < KNN; q++) { bd[q] = 1e30f; bi[q] = -1; }

    for (int s = 0; s < KSEG; s++) {
        const int base = (i * KSEG + s) * KNN;
#pragma unroll
        for (int e = 0; e < KNN; e++) {
            const float dist = cand_d[base + e];
            if (!(dist < bd[KNN - 1])) break;
            float d = dist; int id = cand_i[base + e];
#pragma unroll
            for (int q = 0; q < KNN; q++) {
                const bool sw = d < bd[q];
                const float td = bd[q]; const int ti = bi[q];
                bd[q] = sw ? d : td;   bi[q] = sw ? id : ti;
                d     = sw ? td : d;   id    = sw ? ti : id;
            }
        }
    }

#pragma unroll
    for (int q = 0; q < KNN; q++) idxout[i * KNN + q] = bi[q];
}

// ---------------------------------------------------------------------------
// Kernel 2: AB = X @ [W1top - W1bot | W1bot], b1 folded into A columns
// ---------------------------------------------------------------------------
__global__ void __launch_bounds__(256)
gemm1_kernel(const float* __restrict__ X,
             const float* __restrict__ W1,
             const float* __restrict__ b1,
             float* __restrict__ AB) {
    __shared__ float As[16][65];
    __shared__ float Bs[16][64];

    const int bm = blockIdx.y * 64;
    const int bn = blockIdx.x * 64;
    const int t  = threadIdx.x;
    const int tx = t & 15;
    const int ty = t >> 4;

    float acc[4][4];
#pragma unroll
    for (int a = 0; a < 4; a++)
#pragma unroll
        for (int b = 0; b < 4; b++) acc[a][b] = 0.0f;

    for (int k0 = 0; k0 < CIN; k0 += 16) {
#pragma unroll
        for (int r = 0; r < 4; r++) {
            const int e = t + r * 256;
            const int m = e >> 4, k = e & 15;
            As[k][m] = X[(bm + m) * CIN + k0 + k];
        }
#pragma unroll
        for (int r = 0; r < 4; r++) {
            const int e = t + r * 256;
            const int k = e >> 6, n = e & 63;
            const int gk = k0 + k, gn = bn + n;
            float v;
            if (gn < 256)
                v = W1[gk * 256 + gn] - W1[(gk + 128) * 256 + gn];
            else
                v = W1[(gk + 128) * 256 + (gn - 256)];
            Bs[k][n] = v;
        }
        __syncthreads();

#pragma unroll
        for (int k = 0; k < 16; k++) {
            float a0 = As[k][ty * 4 + 0];
            float a1 = As[k][ty * 4 + 1];
            float a2 = As[k][ty * 4 + 2];
            float a3 = As[k][ty * 4 + 3];
            float b0 = Bs[k][tx * 4 + 0];
            float c1 = Bs[k][tx * 4 + 1];
            float c2 = Bs[k][tx * 4 + 2];
            float b3 = Bs[k][tx * 4 + 3];
            acc[0][0] = fmaf(a0, b0, acc[0][0]); acc[0][1] = fmaf(a0, c1, acc[0][1]);
            acc[0][2] = fmaf(a0, c2, acc[0][2]); acc[0][3] = fmaf(a0, b3, acc[0][3]);
            acc[1][0] = fmaf(a1, b0, acc[1][0]); acc[1][1] = fmaf(a1, c1, acc[1][1]);
            acc[1][2] = fmaf(a1, c2, acc[1][2]); acc[1][3] = fmaf(a1, b3, acc[1][3]);
            acc[2][0] = fmaf(a2, b0, acc[2][0]); acc[2][1] = fmaf(a2, c1, acc[2][1]);
            acc[2][2] = fmaf(a2, c2, acc[2][2]); acc[2][3] = fmaf(a2, b3, acc[2][3]);
            acc[3][0] = fmaf(a3, b0, acc[3][0]); acc[3][1] = fmaf(a3, c1, acc[3][1]);
            acc[3][2] = fmaf(a3, c2, acc[3][2]); acc[3][3] = fmaf(a3, b3, acc[3][3]);
        }
        __syncthreads();
    }

#pragma unroll
    for (int ii = 0; ii < 4; ii++)
#pragma unroll
        for (int jj = 0; jj < 4; jj++) {
            const int gn = bn + tx * 4 + jj;
            const float bias = (gn < 256) ? b1[gn] : 0.0f;
            AB[(bm + ty * 4 + ii) * 512 + gn] = acc[ii][jj] + bias;
        }
}

// ---------------------------------------------------------------------------
// Kernel 2b: split W2 into bf16 hi/lo row-major [k][n] images
// ---------------------------------------------------------------------------
__global__ void __launch_bounds__(256)
w2split_kernel(const float* __restrict__ W2) {
    const int id = blockIdx.x * 256 + threadIdx.x;
    const float4 v = ((const float4*)W2)[id];

    const __nv_bfloat16 h0 = __float2bfloat16_rn(v.x);
    const __nv_bfloat16 h1 = __float2bfloat16_rn(v.y);
    const __nv_bfloat16 h2 = __float2bfloat16_rn(v.z);
    const __nv_bfloat16 h3 = __float2bfloat16_rn(v.w);

    g_W2hi32[id * 2 + 0] = ((uint32_t)__bfloat16_as_ushort(h1) << 16) |
                           (uint32_t)__bfloat16_as_ushort(h0);
    g_W2hi32[id * 2 + 1] = ((uint32_t)__bfloat16_as_ushort(h3) << 16) |
                           (uint32_t)__bfloat16_as_ushort(h2);
    g_W2lo32[id * 2 + 0] = pack_hi2(v.x - __bfloat162float(h0),
                                    v.y - __bfloat162float(h1));
    g_W2lo32[id * 2 + 1] = pack_hi2(v.z - __bfloat162float(h2),
                                    v.w - __bfloat162float(h3));
}

// ---------------------------------------------------------------------------
// Kernel 3: mma.sync bf16 edge GEMM with cp.async double-buffered W2 stream.
// Block = 8 nodes (M=128), N=256, K=256 in 8 chunks of k=32, 2 smem buffers.
// ---------------------------------------------------------------------------
#define SA_HI   0
#define SA_LO   65536
#define SB_BASE 131072
#define SB_BUF  32768          // per buffer: hi 16KB + lo 16KB
#define SM_TOTAL 196608

__global__ void __launch_bounds__(EM_THREADS, 1)
edge_mma_kernel(const float* __restrict__ AB,
                const int* __restrict__ idx,
                const float* __restrict__ b2,
                float* __restrict__ out) {
    extern __shared__ char smem[];
    const uint32_t sbase = smem_u32(smem);
    __shared__ int idxs[128];

    const int t    = threadIdx.x;
    const int lane = t & 31;
    const int wid  = t >> 5;
    const int wm   = wid & 3;
    const int wn   = wid >> 2;
    const int i0   = blockIdx.x * NODES_PB;

    if (t < 128) idxs[t] = idx[i0 * KNN + t];
    __syncthreads();

    // ---- prologue: async-load W2 chunk 0 (overlaps gather phase) ----
    {
#pragma unroll
        for (int ii = 0; ii < 2; ii++) {
            const int e = t + ii * EM_THREADS;       // 0..1023
            const int row = e >> 5, c = e & 31;
            const uint32_t dst = sbase + SB_BASE + row * 512 + ((c ^ (row & 7)) * 16);
            const int src = row * 32 + c;
            CP_ASYNC16(dst, (const uint4*)g_W2hi32 + src);
            CP_ASYNC16(dst + 16384, (const uint4*)g_W2lo32 + src);
        }
        CP_ASYNC_COMMIT();
    }

    // ---- Phase A: gather + relu + bf16 split -> smem (rows = edges) ----
    {
        const int r = t >> 2;
        const int q = t & 3;
        const int j = idxs[r];
        const float4* arow = (const float4*)(AB + (size_t)(i0 + (r >> 4)) * 512) + q * 16;
        const float4* brow = (const float4*)(AB + (size_t)j * 512 + 256) + q * 16;
        const int sw_r = r & 7;
        char* smem_c = smem;
#pragma unroll
        for (int w = 0; w < 8; w++) {
            const float4 a0 = arow[w * 2 + 0];
            const float4 a1 = arow[w * 2 + 1];
            const float4 e0 = brow[w * 2 + 0];
            const float4 e1 = brow[w * 2 + 1];
            const float v0 = fmaxf(a0.x + e0.x, 0.0f);
            const float v1 = fmaxf(a0.y + e0.y, 0.0f);
            const float v2 = fmaxf(a0.z + e0.z, 0.0f);
            const float v3 = fmaxf(a0.w + e0.w, 0.0f);
            const float v4 = fmaxf(a1.x + e1.x, 0.0f);
            const float v5 = fmaxf(a1.y + e1.y, 0.0f);
            const float v6 = fmaxf(a1.z + e1.z, 0.0f);
            const float v7 = fmaxf(a1.w + e1.w, 0.0f);
            const __nv_bfloat16 h0 = __float2bfloat16_rn(v0);
            const __nv_bfloat16 h1 = __float2bfloat16_rn(v1);
            const __nv_bfloat16 h2 = __float2bfloat16_rn(v2);
            const __nv_bfloat16 h3 = __float2bfloat16_rn(v3);
            const __nv_bfloat16 h4 = __float2bfloat16_rn(v4);
            const __nv_bfloat16 h5 = __float2bfloat16_rn(v5);
            const __nv_bfloat16 h6 = __float2bfloat16_rn(v6);
            const __nv_bfloat16 h7 = __float2bfloat16_rn(v7);
            uint4 H, L;
            H.x = ((uint32_t)__bfloat16_as_ushort(h1) << 16) | __bfloat16_as_ushort(h0);
            H.y = ((uint32_t)__bfloat16_as_ushort(h3) << 16) | __bfloat16_as_ushort(h2);
            H.z = ((uint32_t)__bfloat16_as_ushort(h5) << 16) | __bfloat16_as_ushort(h4);
            H.w = ((uint32_t)__bfloat16_as_ushort(h7) << 16) | __bfloat16_as_ushort(h6);
            L.x = pack_hi2(v0 - __bfloat162float(h0), v1 - __bfloat162float(h1));
            L.y = pack_hi2(v2 - __bfloat162float(h2), v3 - __bfloat162float(h3));
            L.z = pack_hi2(v4 - __bfloat162float(h4), v5 - __bfloat162float(h5));
            L.w = pack_hi2(v6 - __bfloat162float(h6), v7 - __bfloat162float(h7));
            const int c = (q * 8 + w) ^ sw_r;
            *(uint4*)(smem_c + SA_HI + r * 512 + c * 16) = H;
            *(uint4*)(smem_c + SA_LO + r * 512 + c * 16) = L;
        }
    }
    __syncthreads();

    // ---- Main loop: 8 chunks of k=32, double-buffered ----
    float D[2][8][4];
#pragma unroll
    for (int mt = 0; mt < 2; mt++)
#pragma unroll
        for (int f = 0; f < 8; f++)
#pragma unroll
            for (int c = 0; c < 4; c++) D[mt][f][c] = 0.0f;

    const int a_row  = wm * 32 + (lane & 15);
    const int a_swz  = a_row & 7;
    const uint32_t a_base_hi = sbase + SA_HI + a_row * 512;
    const uint32_t a_base_lo = sbase + SA_LO + a_row * 512;
    const int b_krow  = lane & 15;
    const int b_cbase = wn * 8 + (lane >> 4);

    for (int kc = 0; kc < 8; kc++) {
        if (kc < 7) {
            const int b = (kc + 1) & 1;
#pragma unroll
            for (int ii = 0; ii < 2; ii++) {
                const int e = t + ii * EM_THREADS;
                const int row = e >> 5, c = e & 31;
                const uint32_t dst = sbase + SB_BASE + b * SB_BUF +
                                     row * 512 + ((c ^ (row & 7)) * 16);
                const int src = ((kc + 1) * 32 + row) * 32 + c;
                CP_ASYNC16(dst, (const uint4*)g_W2hi32 + src);
                CP_ASYNC16(dst + 16384, (const uint4*)g_W2lo32 + src);
            }
            CP_ASYNC_COMMIT();
            CP_ASYNC_WAIT(1);
        } else {
            CP_ASYNC_WAIT(0);
        }
        __syncthreads();

        const uint32_t sb = sbase + SB_BASE + (kc & 1) * SB_BUF;
#pragma unroll
        for (int kt = 0; kt < 2; kt++) {
            const int kg = kc * 2 + kt;
            uint32_t ah[2][4], al[2][4];
#pragma unroll
            for (int mt = 0; mt < 2; mt++) {
                const uint32_t roff = mt * 16 * 512;
                const uint32_t c = (uint32_t)((kg * 2 + (lane >> 4)) ^ a_swz) * 16;
                ldsm_x4(ah[mt][0], ah[mt][1], ah[mt][2], ah[mt][3], a_base_hi + roff + c);
                ldsm_x4(al[mt][0], al[mt][1], al[mt][2], al[mt][3], a_base_lo + roff + c);
            }
#pragma unroll
            for (int g = 0; g < 4; g++) {
                const int krow = kt * 16 + b_krow;
                const uint32_t c = (uint32_t)((b_cbase + g * 2) ^ (krow & 7)) * 16;
                const uint32_t baddr = sb + krow * 512 + c;
                uint32_t bh0, bh1, bh2, bh3, bl0, bl1, bl2, bl3;
                ldsm_x4_t(bh0, bh1, bh2, bh3, baddr);
                ldsm_x4_t(bl0, bl1, bl2, bl3, baddr + 16384);
#pragma unroll
                for (int mt = 0; mt < 2; mt++) {
                    float* d0 = D[mt][g * 2 + 0];
                    float* d1 = D[mt][g * 2 + 1];
                    mma_bf16(d0[0], d0[1], d0[2], d0[3],
                             ah[mt][0], ah[mt][1], ah[mt][2], ah[mt][3], bh0, bh1);
                    mma_bf16(d0[0], d0[1], d0[2], d0[3],
                             ah[mt][0], ah[mt][1], ah[mt][2], ah[mt][3], bl0, bl1);
                    mma_bf16(d0[0], d0[1], d0[2], d0[3],
                             al[mt][0], al[mt][1], al[mt][2], al[mt][3], bh0, bh1);
                    mma_bf16(d1[0], d1[1], d1[2], d1[3],
                             ah[mt][0], ah[mt][1], ah[mt][2], ah[mt][3], bh2, bh3);
                    mma_bf16(d1[0], d1[1], d1[2], d1[3],
                             ah[mt][0], ah[mt][1], ah[mt][2], ah[mt][3], bl2, bl3);
                    mma_bf16(d1[0], d1[1], d1[2], d1[3],
                             al[mt][0], al[mt][1], al[mt][2], al[mt][3], bh2, bh3);
                }
            }
        }
        __syncthreads();
    }

    // ---- Epilogue: max over each node's 16 rows (warp-local) + b2 ----
#pragma unroll
    for (int mt = 0; mt < 2; mt++) {
        const int node = i0 + wm * 2 + mt;
#pragma unroll
        for (int f = 0; f < 8; f++) {
            float m0 = fmaxf(D[mt][f][0], D[mt][f][2]);
            float m1 = fmaxf(D[mt][f][1], D[mt][f][3]);
            m0 = fmaxf(m0, __shfl_xor_sync(0xffffffffu, m0, 4));
            m1 = fmaxf(m1, __shfl_xor_sync(0xffffffffu, m1, 4));
            m0 = fmaxf(m0, __shfl_xor_sync(0xffffffffu, m0, 8));
            m1 = fmaxf(m1, __shfl_xor_sync(0xffffffffu, m1, 8));
            m0 = fmaxf(m0, __shfl_xor_sync(0xffffffffu, m0, 16));
            m1 = fmaxf(m1, __shfl_xor_sync(0xffffffffu, m1, 16));
            if ((lane >> 2) == 0) {
                const int col = wn * 64 + f * 8 + 2 * (lane & 3);
                float2 o;
                o.x = m0 + b2[col];
                o.y = m1 + b2[col + 1];
                *(float2*)(out + (size_t)node * DDIM + col) = o;
            }
        }
    }
}

// ---------------------------------------------------------------------------
// Launch
// ---------------------------------------------------------------------------
extern "C" void kernel_launch(void* const* d_in, const int* in_sizes, int n_in,
                              void* d_out, int out_size) {
    const float* x   = (const float*)d_in[0];
    const float* pos = (const float*)d_in[1];
    const float* W1  = (const float*)d_in[2];
    const float* b1  = (const float*)d_in[3];
    const float* W2  = (const float*)d_in[4];
    const float* b2  = (const float*)d_in[5];
    float* out = (float*)d_out;
    (void)in_sizes; (void)n_in; (void)out_size;

    int*   idx_ptr = nullptr;
    float* ab_ptr  = nullptr;
    float* cd_ptr  = nullptr;
    int*   ci_ptr  = nullptr;
    cudaGetSymbolAddress((void**)&idx_ptr, g_idx);
    cudaGetSymbolAddress((void**)&ab_ptr, g_AB);
    cudaGetSymbolAddress((void**)&cd_ptr, g_cand_d);
    cudaGetSymbolAddress((void**)&ci_ptr, g_cand_i);

    static bool attr_done = false;
    if (!attr_done) {
        cudaFuncSetAttribute(edge_mma_kernel,
                             cudaFuncAttributeMaxDynamicSharedMemorySize, SM_TOTAL);
        attr_done = true;
    }

    knn_part_kernel<<<dim3(NPTS / 512, KSEG), 256>>>(pos, cd_ptr, ci_ptr);
    knn_merge_kernel<<<NPTS / 256, 256>>>(cd_ptr, ci_ptr, idx_ptr);
    gemm1_kernel<<<dim3(512 / 64, NPTS / 64), 256>>>(x, W1, b1, ab_ptr);
    w2split_kernel<<<64, 256>>>(W2);
    edge_mma_kernel<<<NPTS / NODES_PB, EM_THREADS, SM_TOTAL>>>(ab_ptr, idx_ptr, b2, out);
}